// round 11
// baseline (speedup 1.0000x reference)
#include <cuda_runtime.h>
#include <cstdint>

#define B_   2
#define T_   2048
#define C_   2048
#define NH   16
#define NKV  4
#define HD   128
#define MROWS (B_*T_)          // 4096
#define KVC  (NKV*HD)          // 1024
#define QKVN (C_ + 2*KVC)      // 4096 (q | k | v)

__device__ float g_qkv[MROWS * QKVN];
__device__ float g_y[MROWS * C_];     // k-permuted channel layout (see round_perm)
__device__ float g_xr[MROWS * C_];    // k-permuted
__device__ float g_wqkv[QKVN * C_];   // k-permuted
__device__ float g_wo[C_ * C_];       // k-permuted

// ---------------------------------------------------------------------------
__device__ __forceinline__ uint32_t smem_u32(const void* p) {
    uint32_t a;
    asm("{ .reg .u64 t; cvta.to.shared.u64 t, %1; cvt.u32.u64 %0, t; }" : "=r"(a) : "l"(p));
    return a;
}
__device__ __forceinline__ float tf32r(float x) {
    uint32_t u;
    asm("cvt.rna.tf32.f32 %0, %1;" : "=r"(u) : "f"(x));
    return __uint_as_float(u);
}
#define CPA16(s, g) asm volatile("cp.async.cg.shared.global [%0], [%1], 16;" :: "r"(s), "l"(g) : "memory")
#define CPA_COMMIT() asm volatile("cp.async.commit_group;" ::: "memory")
#define CPA_WAIT2()  asm volatile("cp.async.wait_group 2;" ::: "memory")

__device__ __forceinline__ void mma16n8k8(float d[4], const uint32_t a[4], const uint32_t b[2]) {
    asm volatile(
        "mma.sync.aligned.m16n8k8.row.col.f32.tf32.tf32.f32 "
        "{%0,%1,%2,%3}, {%4,%5,%6,%7}, {%8,%9}, {%0,%1,%2,%3};"
        : "+f"(d[0]), "+f"(d[1]), "+f"(d[2]), "+f"(d[3])
        : "r"(a[0]), "r"(a[1]), "r"(a[2]), "r"(a[3]), "r"(b[0]), "r"(b[1]));
}

// ---------------------------------------------------------------------------
// tf32 tensor-core GEMM over k-PERMUTED operands.
// Permutation (within each 32-k group): element k stored at (k&3)*8 + (k>>2).
// => fragment k-pair {8kk+tq, 8kk+tq+4} sits at {tq*8+2kk, tq*8+2kk+1};
//    one LDS.128 at tq*8+4h serves the kk-pair (2h, 2h+1).
// 128x256 block, 8 warps (64x64 warp tile), KT=32, 4-stage single-barrier ring.
// mode=1: fused RoPE (cols<3072) + tf32 rounding of output (QKV projection).
// ---------------------------------------------------------------------------
#define KT 32
#define TPITCH 36
#define A_TF (128 * TPITCH)                 // 4608 floats
#define B_TF (256 * TPITCH)                 // 9216 floats
#define STAGE_F (A_TF + B_TF)               // 13824 floats
#define STAGE_B (STAGE_F * 4)               // 55296 bytes
#define GEMM_SMEM (4 * STAGE_B)             // 221184 B

__device__ __forceinline__ void g_load_stage(uint32_t sdst,
        const float* __restrict__ A, const float* __restrict__ Bm,
        int m0, int n0, int k0, int K, int t)
{
#pragma unroll
    for (int i = 0; i < 4; i++) {
        int c = t + (i << 8);
        int row = c >> 3, q4 = c & 7;
        CPA16(sdst + (uint32_t)(row * TPITCH + q4 * 4) * 4,
              A + (size_t)(m0 + row) * K + k0 + (q4 << 2));
    }
#pragma unroll
    for (int i = 0; i < 8; i++) {
        int c = t + (i << 8);
        int row = c >> 3, q4 = c & 7;
        CPA16(sdst + (uint32_t)(A_TF + row * TPITCH + q4 * 4) * 4,
              Bm + (size_t)(n0 + row) * K + k0 + (q4 << 2));
    }
}

__global__ __launch_bounds__(256, 1)
void gemm_tc(const float* __restrict__ A, const float* __restrict__ Bm,
             float* __restrict__ Cm, int M, int N, int K, int mode,
             const float* __restrict__ fc, const float* __restrict__ fs)
{
    extern __shared__ __align__(16) float sm[];
    const uint32_t sbase = smem_u32(sm);
    const int t = threadIdx.x, wid = t >> 5, lane = t & 31;
    const int q = lane >> 2, tq = lane & 3;
    const int wm = wid & 1, wn = wid >> 1;           // 2(m) x 4(n) warps
    const int m0 = blockIdx.y * 128, n0 = blockIdx.x * 256;

    float d[4][8][4];
#pragma unroll
    for (int mi = 0; mi < 4; mi++)
#pragma unroll
        for (int ni = 0; ni < 8; ni++)
#pragma unroll
            for (int r = 0; r < 4; r++) d[mi][ni][r] = 0.0f;

#pragma unroll
    for (int s = 0; s < 3; s++) {
        g_load_stage(sbase + (uint32_t)s * STAGE_B, A, Bm, m0, n0, s * KT, K, t);
        CPA_COMMIT();
    }

    const int NK = K / KT;                           // 64
    for (int it = 0; it < NK; it++) {
        CPA_WAIT2();
        __syncthreads();
        const float* As = sm + (it & 3) * STAGE_F;
        const float* Bs = As + A_TF;

#pragma unroll
        for (int h2 = 0; h2 < 2; h2++) {             // kk-pair (2h2, 2h2+1)
            float4 Af[4][2];
#pragma unroll
            for (int mi = 0; mi < 4; mi++) {
                const float* ap = As + (wm * 64 + mi * 16 + q) * TPITCH + tq * 8 + 4 * h2;
                Af[mi][0] = *(const float4*)ap;
                Af[mi][1] = *(const float4*)(ap + 8 * TPITCH);
            }
            float4 Bf[8];
#pragma unroll
            for (int ni = 0; ni < 8; ni++)
                Bf[ni] = *(const float4*)(Bs + (wn * 64 + ni * 8 + q) * TPITCH + tq * 8 + 4 * h2);

            // kk = 2*h2
#pragma unroll
            for (int mi = 0; mi < 4; mi++) {
                uint32_t a[4] = {__float_as_uint(Af[mi][0].x), __float_as_uint(Af[mi][1].x),
                                 __float_as_uint(Af[mi][0].y), __float_as_uint(Af[mi][1].y)};
#pragma unroll
                for (int ni = 0; ni < 8; ni++) {
                    uint32_t b[2] = {__float_as_uint(Bf[ni].x), __float_as_uint(Bf[ni].y)};
                    mma16n8k8(d[mi][ni], a, b);
                }
            }
            // kk = 2*h2+1
#pragma unroll
            for (int mi = 0; mi < 4; mi++) {
                uint32_t a[4] = {__float_as_uint(Af[mi][0].z), __float_as_uint(Af[mi][1].z),
                                 __float_as_uint(Af[mi][0].w), __float_as_uint(Af[mi][1].w)};
#pragma unroll
                for (int ni = 0; ni < 8; ni++) {
                    uint32_t b[2] = {__float_as_uint(Bf[ni].z), __float_as_uint(Bf[ni].w)};
                    mma16n8k8(d[mi][ni], a, b);
                }
            }
        }

        const int itp = it + 3;
        if (itp < NK)
            g_load_stage(sbase + (uint32_t)(itp & 3) * STAGE_B, A, Bm, m0, n0, itp * KT, K, t);
        CPA_COMMIT();
    }

    // epilogue (N-dim: normal layout)
#pragma unroll
    for (int mi = 0; mi < 4; mi++) {
        int row = m0 + wm * 64 + mi * 16 + q;
        int row2 = row + 8;
#pragma unroll
        for (int ni = 0; ni < 8; ni++) {
            int col = n0 + wn * 64 + ni * 8 + 2 * tq;
            float v0 = d[mi][ni][0], v1 = d[mi][ni][1];
            float v2 = d[mi][ni][2], v3 = d[mi][ni][3];
            if (mode) {
                if (col < C_ + KVC) {
                    int i = (col & 127) >> 1;
                    int tp1 = row & (T_ - 1), tp2 = row2 & (T_ - 1);
                    float c1 = fc[tp1 * 64 + i], s1 = fs[tp1 * 64 + i];
                    float c2 = fc[tp2 * 64 + i], s2 = fs[tp2 * 64 + i];
                    float r0 = v0 * c1 - v1 * s1, r1 = v0 * s1 + v1 * c1;
                    float r2 = v2 * c2 - v3 * s2, r3 = v2 * s2 + v3 * c2;
                    v0 = r0; v1 = r1; v2 = r2; v3 = r3;
                }
                v0 = tf32r(v0); v1 = tf32r(v1);
                v2 = tf32r(v2); v3 = tf32r(v3);
            }
            *(float2*)(Cm + (size_t)row  * N + col) = make_float2(v0, v1);
            *(float2*)(Cm + (size_t)row2 * N + col) = make_float2(v2, v3);
        }
    }
}

// ---------------------------------------------------------------------------
// round to tf32 AND permute k-layout: groups of 32, element k -> (k&3)*8+(k>>2).
// float4 at flat index i covers k=4i..4i+3 -> positions {0,8,16,24}+ (i&7).
// ---------------------------------------------------------------------------
__global__ __launch_bounds__(256)
void round_perm(const float4* __restrict__ in, float* __restrict__ out, int n4)
{
    for (int i = blockIdx.x * 256 + threadIdx.x; i < n4; i += gridDim.x * 256) {
        float4 v = in[i];
        float* o = out + ((size_t)(i >> 3) << 5) + (i & 7);
        o[0]  = tf32r(v.x);
        o[8]  = tf32r(v.y);
        o[16] = tf32r(v.z);
        o[24] = tf32r(v.w);
    }
}

// ---------------------------------------------------------------------------
// Flash attention on mma.sync tf32 (round-10 kernel; only the y epilogue
// changes: writes k-PERMUTED channel layout for the wo gemm).
// ---------------------------------------------------------------------------
#define BM 128
#define BN 64
#define QP 132
#define KP 132
#define PP 68
#define ATT_SMEM ((128*QP + 64*KP + 64*KP + 128*PP) * 4)

__global__ __launch_bounds__(256, 1)
void attn_mma()
{
    extern __shared__ __align__(16) float smA[];
    float* Qs = smA;
    float* Ks = Qs + 128 * QP;
    float* Vs = Ks + 64 * KP;
    float* Ps = Vs + 64 * KP;

    const int t = threadIdx.x, w = t >> 5, lane = t & 31;
    const int q = lane >> 2, tq = lane & 3;
    const int qb = (int)gridDim.x - 1 - (int)blockIdx.x;
    const int h = blockIdx.y, b = blockIdx.z;
    const int kvh = h >> 2;
    const float scale = 0.08838834764831845f;
    const int wr = w * 16;

    {
        const float* qbase = g_qkv + ((size_t)(b * T_ + qb * BM)) * QKVN + h * HD;
#pragma unroll
        for (int i = 0; i < 16; i++) {
            int f = t + (i << 8);
            int row = f >> 5, d4 = f & 31;
            *(float4*)(Qs + row * QP + (d4 << 2)) =
                *(const float4*)(qbase + (size_t)row * QKVN + (d4 << 2));
        }
    }
    __syncthreads();

    uint32_t qf[16][4];
#pragma unroll
    for (int ks = 0; ks < 16; ks++) {
        const uint32_t* qp = (const uint32_t*)(Qs + (wr + q) * QP + ks * 8 + tq);
        qf[ks][0] = qp[0]; qf[ks][1] = qp[8 * QP];
        qf[ks][2] = qp[4]; qf[ks][3] = qp[8 * QP + 4];
    }

    float o[16][4];
#pragma unroll
    for (int nf = 0; nf < 16; nf++)
#pragma unroll
        for (int r = 0; r < 4; r++) o[nf][r] = 0.0f;
    float m0 = -1e30f, m1 = -1e30f, l0 = 0.0f, l1 = 0.0f;

    const int ntiles = 2 * qb + 2;
    for (int kb = 0; kb < ntiles; kb++) {
        __syncthreads();
        {
            const float* kbase = g_qkv + ((size_t)(b * T_ + kb * BN)) * QKVN + C_ + kvh * HD;
            const float* vbase = g_qkv + ((size_t)(b * T_ + kb * BN)) * QKVN + C_ + KVC + kvh * HD;
#pragma unroll
            for (int i = 0; i < 8; i++) {
                int f = t + (i << 8);
                int row = f >> 5, d4 = f & 31;
                *(float4*)(Ks + row * KP + (d4 << 2)) =
                    *(const float4*)(kbase + (size_t)row * QKVN + (d4 << 2));
                *(float4*)(Vs + row * KP + (d4 << 2)) =
                    *(const float4*)(vbase + (size_t)row * QKVN + (d4 << 2));
            }
        }
        __syncthreads();

        float s[8][4];
#pragma unroll
        for (int nf = 0; nf < 8; nf++)
#pragma unroll
            for (int r = 0; r < 4; r++) s[nf][r] = 0.0f;

#pragma unroll
        for (int ks = 0; ks < 16; ks++) {
#pragma unroll
            for (int nf = 0; nf < 8; nf++) {
                const uint32_t* kp = (const uint32_t*)(Ks + (nf * 8 + q) * KP + ks * 8 + tq);
                uint32_t bb[2] = {kp[0], kp[4]};
                mma16n8k8(s[nf], qf[ks], bb);
            }
        }

#pragma unroll
        for (int nf = 0; nf < 8; nf++)
#pragma unroll
            for (int r = 0; r < 4; r++) s[nf][r] *= scale;

        if (kb >= 2 * qb) {
            int ig0 = qb * BM + wr + q, ig1 = ig0 + 8;
#pragma unroll
            for (int nf = 0; nf < 8; nf++) {
                int jg = kb * BN + nf * 8 + 2 * tq;
                if (jg     > ig0) s[nf][0] = -1e30f;
                if (jg + 1 > ig0) s[nf][1] = -1e30f;
                if (jg     > ig1) s[nf][2] = -1e30f;
                if (jg + 1 > ig1) s[nf][3] = -1e30f;
            }
        }

        float mx0 = s[0][0], mx1 = s[0][2];
#pragma unroll
        for (int nf = 0; nf < 8; nf++) {
            mx0 = fmaxf(mx0, fmaxf(s[nf][0], s[nf][1]));
            mx1 = fmaxf(mx1, fmaxf(s[nf][2], s[nf][3]));
        }
        mx0 = fmaxf(mx0, __shfl_xor_sync(0xffffffffu, mx0, 1));
        mx0 = fmaxf(mx0, __shfl_xor_sync(0xffffffffu, mx0, 2));
        mx1 = fmaxf(mx1, __shfl_xor_sync(0xffffffffu, mx1, 1));
        mx1 = fmaxf(mx1, __shfl_xor_sync(0xffffffffu, mx1, 2));
        float mn0 = fmaxf(m0, mx0), mn1 = fmaxf(m1, mx1);
        float c0 = __expf(m0 - mn0), c1 = __expf(m1 - mn1);
        float rs0 = 0.0f, rs1 = 0.0f;
#pragma unroll
        for (int nf = 0; nf < 8; nf++) {
            s[nf][0] = __expf(s[nf][0] - mn0);
            s[nf][1] = __expf(s[nf][1] - mn0);
            s[nf][2] = __expf(s[nf][2] - mn1);
            s[nf][3] = __expf(s[nf][3] - mn1);
            rs0 += s[nf][0] + s[nf][1];
            rs1 += s[nf][2] + s[nf][3];
        }
        rs0 += __shfl_xor_sync(0xffffffffu, rs0, 1);
        rs0 += __shfl_xor_sync(0xffffffffu, rs0, 2);
        rs1 += __shfl_xor_sync(0xffffffffu, rs1, 1);
        rs1 += __shfl_xor_sync(0xffffffffu, rs1, 2);
        l0 = l0 * c0 + rs0;  l1 = l1 * c1 + rs1;
        m0 = mn0;  m1 = mn1;
#pragma unroll
        for (int nf = 0; nf < 16; nf++) {
            o[nf][0] *= c0; o[nf][1] *= c0;
            o[nf][2] *= c1; o[nf][3] *= c1;
        }

#pragma unroll
        for (int nf = 0; nf < 8; nf++) {
            *(float2*)(Ps + (wr + q) * PP + nf * 8 + 2 * tq) =
                make_float2(tf32r(s[nf][0]), tf32r(s[nf][1]));
            *(float2*)(Ps + (wr + q + 8) * PP + nf * 8 + 2 * tq) =
                make_float2(tf32r(s[nf][2]), tf32r(s[nf][3]));
        }
        __syncwarp();

#pragma unroll
        for (int ks = 0; ks < 8; ks++) {
            uint32_t a[4];
            const uint32_t* pp = (const uint32_t*)(Ps + (wr + q) * PP + ks * 8 + tq);
            a[0] = pp[0]; a[1] = pp[8 * PP]; a[2] = pp[4]; a[3] = pp[8 * PP + 4];
#pragma unroll
            for (int nf = 0; nf < 16; nf++) {
                const uint32_t* vp = (const uint32_t*)(Vs + (ks * 8 + tq) * KP + nf * 8 + q);
                uint32_t bb[2] = {vp[0], vp[4 * KP]};
                mma16n8k8(o[nf], a, bb);
            }
        }
    }

    // epilogue: normalize, tf32-round, store y in k-PERMUTED channel layout
    float i0 = 1.0f / l0, i1 = 1.0f / l1;
    int r0 = qb * BM + wr + q;
    float* yb0 = g_y + ((size_t)(b * T_ + r0)) * C_ + h * HD;
    float* yb1 = yb0 + 8 * C_;
#pragma unroll
    for (int nf = 0; nf < 16; nf++) {
        int cg = nf * 8 + 2 * tq;
        int c0i = cg & 31, c1i = c0i + 1;
        int p0 = ((c0i & 3) << 3) + (c0i >> 2);
        int p1 = ((c1i & 3) << 3) + (c1i >> 2);
        float* g0 = yb0 + (cg & ~31);
        float* g1 = yb1 + (cg & ~31);
        g0[p0] = tf32r(o[nf][0] * i0);
        g0[p1] = tf32r(o[nf][1] * i0);
        g1[p0] = tf32r(o[nf][2] * i1);
        g1[p1] = tf32r(o[nf][3] * i1);
    }
}

// ---------------------------------------------------------------------------
extern "C" void kernel_launch(void* const* d_in, const int* in_sizes, int n_in,
                              void* d_out, int out_size)
{
    const float* x  = (const float*)d_in[0];
    const float* fc = (const float*)d_in[1];
    const float* fs = (const float*)d_in[2];
    const float* wq = (const float*)d_in[3];
    const float* wk = (const float*)d_in[4];
    const float* wv = (const float*)d_in[5];
    const float* wo = (const float*)d_in[6];
    float* out = (float*)d_out;

    float *qkv, *y, *xr, *wqkv, *rwo;
    cudaGetSymbolAddress((void**)&qkv,  g_qkv);
    cudaGetSymbolAddress((void**)&y,    g_y);
    cudaGetSymbolAddress((void**)&xr,   g_xr);
    cudaGetSymbolAddress((void**)&wqkv, g_wqkv);
    cudaGetSymbolAddress((void**)&rwo,  g_wo);

    // round to tf32 + permute k-layout (groups of 32 along the contraction dim)
    round_perm<<<2048, 256>>>((const float4*)x,  xr, MROWS * C_ / 4);
    round_perm<<<1024, 256>>>((const float4*)wq, wqkv, C_ * C_ / 4);
    round_perm<<<512,  256>>>((const float4*)wk, wqkv + (size_t)C_ * C_, KVC * C_ / 4);
    round_perm<<<512,  256>>>((const float4*)wv, wqkv + (size_t)(C_ + KVC) * C_, KVC * C_ / 4);
    round_perm<<<1024, 256>>>((const float4*)wo, rwo, C_ * C_ / 4);

    cudaFuncSetAttribute(gemm_tc, cudaFuncAttributeMaxDynamicSharedMemorySize, GEMM_SMEM);

    // fused QKV projection + RoPE + tf32 rounding (output normal layout)
    gemm_tc<<<dim3(QKVN / 256, MROWS / 128), 256, GEMM_SMEM>>>(
        xr, wqkv, qkv, MROWS, QKVN, C_, 1, fc, fs);

    cudaFuncSetAttribute(attn_mma, cudaFuncAttributeMaxDynamicSharedMemorySize, ATT_SMEM);
    attn_mma<<<dim3(T_ / BM, NH, B_), 256, ATT_SMEM>>>();

    // output projection (A=y and B=wo both k-permuted; output normal)
    gemm_tc<<<dim3(C_ / 256, MROWS / 128), 256, GEMM_SMEM>>>(
        y, rwo, out, MROWS, C_, C_, 0, nullptr, nullptr);
}

// round 13
// speedup vs baseline: 1.3837x; 1.3837x over previous
#include <cuda_runtime.h>
#include <cuda_fp16.h>
#include <cstdint>

#define B_   2
#define T_   2048
#define C_   2048
#define NH   16
#define NKV  4
#define HD   128
#define MROWS (B_*T_)          // 4096
#define KVC  (NKV*HD)          // 1024
#define QKVN (C_ + 2*KVC)      // 4096 (q | k | v)

__device__ float  g_qkv[MROWS * QKVN];    // fp32, tf32-rounded (attention input)
__device__ __half g_yh[MROWS * C_];       // fp16 attention output (wo gemm input)
__device__ __half g_xh[MROWS * C_];       // fp16 x
__device__ __half g_wqkvh[QKVN * C_];     // fp16 wq|wk|wv
__device__ __half g_woh[C_ * C_];         // fp16 wo

// ---------------------------------------------------------------------------
__device__ __forceinline__ uint32_t smem_u32(const void* p) {
    uint32_t a;
    asm("{ .reg .u64 t; cvta.to.shared.u64 t, %1; cvt.u32.u64 %0, t; }" : "=r"(a) : "l"(p));
    return a;
}
__device__ __forceinline__ float tf32r(float x) {
    uint32_t u;
    asm("cvt.rna.tf32.f32 %0, %1;" : "=r"(u) : "f"(x));
    return __uint_as_float(u);
}
#define CPA16(s, g) asm volatile("cp.async.cg.shared.global [%0], [%1], 16;" :: "r"(s), "l"(g) : "memory")
#define CPA_COMMIT() asm volatile("cp.async.commit_group;" ::: "memory")
#define CPA_WAIT2()  asm volatile("cp.async.wait_group 2;" ::: "memory")

// tf32 mma (attention, unchanged path)
__device__ __forceinline__ void mma16n8k8(float d[4], const uint32_t a[4], const uint32_t b[2]) {
    asm volatile(
        "mma.sync.aligned.m16n8k8.row.col.f32.tf32.tf32.f32 "
        "{%0,%1,%2,%3}, {%4,%5,%6,%7}, {%8,%9}, {%0,%1,%2,%3};"
        : "+f"(d[0]), "+f"(d[1]), "+f"(d[2]), "+f"(d[3])
        : "r"(a[0]), "r"(a[1]), "r"(a[2]), "r"(a[3]), "r"(b[0]), "r"(b[1]));
}
// fp16 mma, fp32 accum (projection GEMMs)
__device__ __forceinline__ void mma16n8k16h(float d[4], const uint32_t a[4], const uint32_t b[2]) {
    asm volatile(
        "mma.sync.aligned.m16n8k16.row.col.f32.f16.f16.f32 "
        "{%0,%1,%2,%3}, {%4,%5,%6,%7}, {%8,%9}, {%0,%1,%2,%3};"
        : "+f"(d[0]), "+f"(d[1]), "+f"(d[2]), "+f"(d[3])
        : "r"(a[0]), "r"(a[1]), "r"(a[2]), "r"(a[3]), "r"(b[0]), "r"(b[1]));
}

// ---------------------------------------------------------------------------
// fp16 tensor-core GEMM: C[M,N] = A[M,K]*B[N,K]^T, half in / fp32 out.
// 128x256 block, 8 warps (64x64 warp tile), KT=32, 4-stage single-barrier ring.
// smem pitch 40 halfs: fragment u32 loads land on banks 20q+tq -> conflict-free.
// mode=1: fused RoPE (cols<3072) + tf32 rounding of output (QKV projection).
// ---------------------------------------------------------------------------
#define KT 32
#define HPITCH 40
#define A_HF (128 * HPITCH)                 // 5120 halfs
#define B_HF (256 * HPITCH)                 // 10240 halfs
#define STAGE_HF (A_HF + B_HF)              // 15360 halfs
#define STAGE_B (STAGE_HF * 2)              // 30720 bytes
#define GEMM_SMEM (4 * STAGE_B)             // 122880 B

__device__ __forceinline__ void g_load_stage(uint32_t sdst,
        const __half* __restrict__ A, const __half* __restrict__ Bm,
        int m0, int n0, int k0, int K, int t)
{
#pragma unroll
    for (int i = 0; i < 2; i++) {                    // A: 512 chunks of 8 halfs
        int c = t + (i << 8);
        int row = c >> 2, ch = c & 3;
        CPA16(sdst + (uint32_t)(row * HPITCH + ch * 8) * 2,
              A + (size_t)(m0 + row) * K + k0 + ch * 8);
    }
#pragma unroll
    for (int i = 0; i < 4; i++) {                    // B: 1024 chunks
        int c = t + (i << 8);
        int row = c >> 2, ch = c & 3;
        CPA16(sdst + (uint32_t)(A_HF + row * HPITCH + ch * 8) * 2,
              Bm + (size_t)(n0 + row) * K + k0 + ch * 8);
    }
}

__global__ __launch_bounds__(256, 1)
void gemm_tc(const __half* __restrict__ A, const __half* __restrict__ Bm,
             float* __restrict__ Cm, int M, int N, int K, int mode,
             const float* __restrict__ fc, const float* __restrict__ fs)
{
    extern __shared__ __align__(16) __half smh[];
    const uint32_t sbase = smem_u32(smh);
    const int t = threadIdx.x, wid = t >> 5, lane = t & 31;
    const int q = lane >> 2, tq = lane & 3;
    const int wm = wid & 1, wn = wid >> 1;           // 2(m) x 4(n) warps
    const int m0 = blockIdx.y * 128, n0 = blockIdx.x * 256;

    float d[4][8][4];
#pragma unroll
    for (int mi = 0; mi < 4; mi++)
#pragma unroll
        for (int ni = 0; ni < 8; ni++)
#pragma unroll
            for (int r = 0; r < 4; r++) d[mi][ni][r] = 0.0f;

#pragma unroll
    for (int s = 0; s < 3; s++) {
        g_load_stage(sbase + (uint32_t)s * STAGE_B, A, Bm, m0, n0, s * KT, K, t);
        CPA_COMMIT();
    }

    const int NK = K / KT;                           // 64
    for (int it = 0; it < NK; it++) {
        CPA_WAIT2();
        __syncthreads();
        const __half* Ah = smh + (it & 3) * STAGE_HF;
        const __half* Bh = Ah + A_HF;

#pragma unroll
        for (int ks = 0; ks < 2; ks++) {             // two k16 steps per KT=32
            const int kb = ks * 16;
            uint32_t af[4][4];
#pragma unroll
            for (int mi = 0; mi < 4; mi++) {
                const __half* ap = Ah + (wm * 64 + mi * 16 + q) * HPITCH + kb + 2 * tq;
                af[mi][0] = *(const uint32_t*)ap;
                af[mi][1] = *(const uint32_t*)(ap + 8 * HPITCH);
                af[mi][2] = *(const uint32_t*)(ap + 8);
                af[mi][3] = *(const uint32_t*)(ap + 8 * HPITCH + 8);
            }
            uint32_t bf[8][2];
#pragma unroll
            for (int ni = 0; ni < 8; ni++) {
                const __half* bp = Bh + (wn * 64 + ni * 8 + q) * HPITCH + kb + 2 * tq;
                bf[ni][0] = *(const uint32_t*)bp;
                bf[ni][1] = *(const uint32_t*)(bp + 8);
            }
#pragma unroll
            for (int mi = 0; mi < 4; mi++)
#pragma unroll
                for (int ni = 0; ni < 8; ni++)
                    mma16n8k16h(d[mi][ni], af[mi], bf[ni]);
        }

        const int itp = it + 3;
        if (itp < NK)
            g_load_stage(sbase + (uint32_t)(itp & 3) * STAGE_B, A, Bm, m0, n0, itp * KT, K, t);
        CPA_COMMIT();
    }

    // epilogue
#pragma unroll
    for (int mi = 0; mi < 4; mi++) {
        int row = m0 + wm * 64 + mi * 16 + q;
        int row2 = row + 8;
#pragma unroll
        for (int ni = 0; ni < 8; ni++) {
            int col = n0 + wn * 64 + ni * 8 + 2 * tq;
            float v0 = d[mi][ni][0], v1 = d[mi][ni][1];
            float v2 = d[mi][ni][2], v3 = d[mi][ni][3];
            if (mode) {
                if (col < C_ + KVC) {                 // q or k section: RoPE
                    int i = (col & 127) >> 1;
                    int tp1 = row & (T_ - 1), tp2 = row2 & (T_ - 1);
                    float c1 = fc[tp1 * 64 + i], s1 = fs[tp1 * 64 + i];
                    float c2 = fc[tp2 * 64 + i], s2 = fs[tp2 * 64 + i];
                    float r0 = v0 * c1 - v1 * s1, r1 = v0 * s1 + v1 * c1;
                    float r2 = v2 * c2 - v3 * s2, r3 = v2 * s2 + v3 * c2;
                    v0 = r0; v1 = r1; v2 = r2; v3 = r3;
                }
                v0 = tf32r(v0); v1 = tf32r(v1);
                v2 = tf32r(v2); v3 = tf32r(v3);
            }
            *(float2*)(Cm + (size_t)row  * N + col) = make_float2(v0, v1);
            *(float2*)(Cm + (size_t)row2 * N + col) = make_float2(v2, v3);
        }
    }
}

// ---------------------------------------------------------------------------
// fp32 -> fp16 (round-to-nearest) conversion
// ---------------------------------------------------------------------------
__global__ __launch_bounds__(256)
void round_h(const float4* __restrict__ in, __half2* __restrict__ out, int n4)
{
    for (int i = blockIdx.x * 256 + threadIdx.x; i < n4; i += gridDim.x * 256) {
        float4 v = in[i];
        out[2 * i]     = __floats2half2_rn(v.x, v.y);
        out[2 * i + 1] = __floats2half2_rn(v.z, v.w);
    }
}

// ---------------------------------------------------------------------------
// Flash attention on mma.sync tf32 (round-10 kernel; y epilogue now stores
// fp16 for the fp16 wo gemm — same 10-bit mantissa as the former tf32 round).
// ---------------------------------------------------------------------------
#define BM 128
#define BN 64
#define QP 132
#define KP 132
#define PP 68
#define ATT_SMEM ((128*QP + 64*KP + 64*KP + 128*PP) * 4)

__global__ __launch_bounds__(256, 1)
void attn_mma()
{
    extern __shared__ __align__(16) float smA[];
    float* Qs = smA;
    float* Ks = Qs + 128 * QP;
    float* Vs = Ks + 64 * KP;
    float* Ps = Vs + 64 * KP;

    const int t = threadIdx.x, w = t >> 5, lane = t & 31;
    const int q = lane >> 2, tq = lane & 3;
    const int qb = (int)gridDim.x - 1 - (int)blockIdx.x;
    const int h = blockIdx.y, b = blockIdx.z;
    const int kvh = h >> 2;
    const float scale = 0.08838834764831845f;
    const int wr = w * 16;

    {
        const float* qbase = g_qkv + ((size_t)(b * T_ + qb * BM)) * QKVN + h * HD;
#pragma unroll
        for (int i = 0; i < 16; i++) {
            int f = t + (i << 8);
            int row = f >> 5, d4 = f & 31;
            *(float4*)(Qs + row * QP + (d4 << 2)) =
                *(const float4*)(qbase + (size_t)row * QKVN + (d4 << 2));
        }
    }
    __syncthreads();

    uint32_t qf[16][4];
#pragma unroll
    for (int ks = 0; ks < 16; ks++) {
        const uint32_t* qp = (const uint32_t*)(Qs + (wr + q) * QP + ks * 8 + tq);
        qf[ks][0] = qp[0]; qf[ks][1] = qp[8 * QP];
        qf[ks][2] = qp[4]; qf[ks][3] = qp[8 * QP + 4];
    }

    float o[16][4];
#pragma unroll
    for (int nf = 0; nf < 16; nf++)
#pragma unroll
        for (int r = 0; r < 4; r++) o[nf][r] = 0.0f;
    float m0 = -1e30f, m1 = -1e30f, l0 = 0.0f, l1 = 0.0f;

    const int ntiles = 2 * qb + 2;
    for (int kb = 0; kb < ntiles; kb++) {
        __syncthreads();
        {
            const float* kbase = g_qkv + ((size_t)(b * T_ + kb * BN)) * QKVN + C_ + kvh * HD;
            const float* vbase = g_qkv + ((size_t)(b * T_ + kb * BN)) * QKVN + C_ + KVC + kvh * HD;
#pragma unroll
            for (int i = 0; i < 8; i++) {
                int f = t + (i << 8);
                int row = f >> 5, d4 = f & 31;
                *(float4*)(Ks + row * KP + (d4 << 2)) =
                    *(const float4*)(kbase + (size_t)row * QKVN + (d4 << 2));
                *(float4*)(Vs + row * KP + (d4 << 2)) =
                    *(const float4*)(vbase + (size_t)row * QKVN + (d4 << 2));
            }
        }
        __syncthreads();

        float s[8][4];
#pragma unroll
        for (int nf = 0; nf < 8; nf++)
#pragma unroll
            for (int r = 0; r < 4; r++) s[nf][r] = 0.0f;

#pragma unroll
        for (int ks = 0; ks < 16; ks++) {
#pragma unroll
            for (int nf = 0; nf < 8; nf++) {
                const uint32_t* kp = (const uint32_t*)(Ks + (nf * 8 + q) * KP + ks * 8 + tq);
                uint32_t bb[2] = {kp[0], kp[4]};
                mma16n8k8(s[nf], qf[ks], bb);
            }
        }

#pragma unroll
        for (int nf = 0; nf < 8; nf++)
#pragma unroll
            for (int r = 0; r < 4; r++) s[nf][r] *= scale;

        if (kb >= 2 * qb) {
            int ig0 = qb * BM + wr + q, ig1 = ig0 + 8;
#pragma unroll
            for (int nf = 0; nf < 8; nf++) {
                int jg = kb * BN + nf * 8 + 2 * tq;
                if (jg     > ig0) s[nf][0] = -1e30f;
                if (jg + 1 > ig0) s[nf][1] = -1e30f;
                if (jg     > ig1) s[nf][2] = -1e30f;
                if (jg + 1 > ig1) s[nf][3] = -1e30f;
            }
        }

        float mx0 = s[0][0], mx1 = s[0][2];
#pragma unroll
        for (int nf = 0; nf < 8; nf++) {
            mx0 = fmaxf(mx0, fmaxf(s[nf][0], s[nf][1]));
            mx1 = fmaxf(mx1, fmaxf(s[nf][2], s[nf][3]));
        }
        mx0 = fmaxf(mx0, __shfl_xor_sync(0xffffffffu, mx0, 1));
        mx0 = fmaxf(mx0, __shfl_xor_sync(0xffffffffu, mx0, 2));
        mx1 = fmaxf(mx1, __shfl_xor_sync(0xffffffffu, mx1, 1));
        mx1 = fmaxf(mx1, __shfl_xor_sync(0xffffffffu, mx1, 2));
        float mn0 = fmaxf(m0, mx0), mn1 = fmaxf(m1, mx1);
        float c0 = __expf(m0 - mn0), c1 = __expf(m1 - mn1);
        float rs0 = 0.0f, rs1 = 0.0f;
#pragma unroll
        for (int nf = 0; nf < 8; nf++) {
            s[nf][0] = __expf(s[nf][0] - mn0);
            s[nf][1] = __expf(s[nf][1] - mn0);
            s[nf][2] = __expf(s[nf][2] - mn1);
            s[nf][3] = __expf(s[nf][3] - mn1);
            rs0 += s[nf][0] + s[nf][1];
            rs1 += s[nf][2] + s[nf][3];
        }
        rs0 += __shfl_xor_sync(0xffffffffu, rs0, 1);
        rs0 += __shfl_xor_sync(0xffffffffu, rs0, 2);
        rs1 += __shfl_xor_sync(0xffffffffu, rs1, 1);
        rs1 += __shfl_xor_sync(0xffffffffu, rs1, 2);
        l0 = l0 * c0 + rs0;  l1 = l1 * c1 + rs1;
        m0 = mn0;  m1 = mn1;
#pragma unroll
        for (int nf = 0; nf < 16; nf++) {
            o[nf][0] *= c0; o[nf][1] *= c0;
            o[nf][2] *= c1; o[nf][3] *= c1;
        }

#pragma unroll
        for (int nf = 0; nf < 8; nf++) {
            *(float2*)(Ps + (wr + q) * PP + nf * 8 + 2 * tq) =
                make_float2(tf32r(s[nf][0]), tf32r(s[nf][1]));
            *(float2*)(Ps + (wr + q + 8) * PP + nf * 8 + 2 * tq) =
                make_float2(tf32r(s[nf][2]), tf32r(s[nf][3]));
        }
        __syncwarp();

#pragma unroll
        for (int ks = 0; ks < 8; ks++) {
            uint32_t a[4];
            const uint32_t* pp = (const uint32_t*)(Ps + (wr + q) * PP + ks * 8 + tq);
            a[0] = pp[0]; a[1] = pp[8 * PP]; a[2] = pp[4]; a[3] = pp[8 * PP + 4];
#pragma unroll
            for (int nf = 0; nf < 16; nf++) {
                const uint32_t* vp = (const uint32_t*)(Vs + (ks * 8 + tq) * KP + nf * 8 + q);
                uint32_t bb[2] = {vp[0], vp[4 * KP]};
                mma16n8k8(o[nf], a, bb);
            }
        }
    }

    // epilogue: normalize, store fp16 y (feeds fp16 wo gemm)
    float i0 = 1.0f / l0, i1 = 1.0f / l1;
    int r0 = qb * BM + wr + q;
    __half* yb = g_yh + ((size_t)(b * T_ + r0)) * C_ + h * HD;
#pragma unroll
    for (int nf = 0; nf < 16; nf++) {
        *(__half2*)(yb + nf * 8 + 2 * tq) =
            __floats2half2_rn(o[nf][0] * i0, o[nf][1] * i0);
        *(__half2*)(yb + 8 * C_ + nf * 8 + 2 * tq) =
            __floats2half2_rn(o[nf][2] * i1, o[nf][3] * i1);
    }
}

// ---------------------------------------------------------------------------
extern "C" void kernel_launch(void* const* d_in, const int* in_sizes, int n_in,
                              void* d_out, int out_size)
{
    const float* x  = (const float*)d_in[0];
    const float* fc = (const float*)d_in[1];
    const float* fs = (const float*)d_in[2];
    const float* wq = (const float*)d_in[3];
    const float* wk = (const float*)d_in[4];
    const float* wv = (const float*)d_in[5];
    const float* wo = (const float*)d_in[6];
    float* out = (float*)d_out;

    float *qkv;
    __half *xh, *wqkvh, *woh, *yh;
    cudaGetSymbolAddress((void**)&qkv,   g_qkv);
    cudaGetSymbolAddress((void**)&yh,    g_yh);
    cudaGetSymbolAddress((void**)&xh,    g_xh);
    cudaGetSymbolAddress((void**)&wqkvh, g_wqkvh);
    cudaGetSymbolAddress((void**)&woh,   g_woh);

    // fp32 -> fp16 operand conversion (rn; same mantissa width as tf32)
    round_h<<<2048, 256>>>((const float4*)x,  (__half2*)xh, MROWS * C_ / 4);
    round_h<<<1024, 256>>>((const float4*)wq, (__half2*)wqkvh, C_ * C_ / 4);
    round_h<<<512,  256>>>((const float4*)wk, (__half2*)(wqkvh + (size_t)C_ * C_), KVC * C_ / 4);
    round_h<<<512,  256>>>((const float4*)wv, (__half2*)(wqkvh + (size_t)(C_ + KVC) * C_), KVC * C_ / 4);
    round_h<<<1024, 256>>>((const float4*)wo, (__half2*)woh, C_ * C_ / 4);

    cudaFuncSetAttribute(gemm_tc, cudaFuncAttributeMaxDynamicSharedMemorySize, GEMM_SMEM);

    // fused QKV projection + RoPE + tf32 rounding (fp16 operands, fp32 out)
    gemm_tc<<<dim3(QKVN / 256, MROWS / 128), 256, GEMM_SMEM>>>(
        xh, wqkvh, qkv, MROWS, QKVN, C_, 1, fc, fs);

    cudaFuncSetAttribute(attn_mma, cudaFuncAttributeMaxDynamicSharedMemorySize, ATT_SMEM);
    attn_mma<<<dim3(T_ / BM, NH, B_), 256, ATT_SMEM>>>();

    // output projection (fp16 y, fp16 wo -> fp32 out)
    gemm_tc<<<dim3(C_ / 256, MROWS / 128), 256, GEMM_SMEM>>>(
        yh, woh, out, MROWS, C_, C_, 0, nullptr, nullptr);
}

// round 15
// speedup vs baseline: 1.8144x; 1.3113x over previous
#include <cuda_runtime.h>
#include <cuda_fp16.h>
#include <cstdint>

#define B_   2
#define T_   2048
#define C_   2048
#define NH   16
#define NKV  4
#define HD   128
#define MROWS (B_*T_)          // 4096
#define KVC  (NKV*HD)          // 1024
#define QKVN (C_ + 2*KVC)      // 4096 (q | k | v)

__device__ __half g_qkvh[MROWS * QKVN];   // fp16 q|k|v (RoPE'd q,k)
__device__ __half g_yh[MROWS * C_];       // fp16 attention output
__device__ __half g_xh[MROWS * C_];       // fp16 x
__device__ __half g_wqkvh[QKVN * C_];     // fp16 wq|wk|wv
__device__ __half g_woh[C_ * C_];         // fp16 wo

// ---------------------------------------------------------------------------
__device__ __forceinline__ uint32_t smem_u32(const void* p) {
    uint32_t a;
    asm("{ .reg .u64 t; cvta.to.shared.u64 t, %1; cvt.u32.u64 %0, t; }" : "=r"(a) : "l"(p));
    return a;
}
#define CPA16(s, g) asm volatile("cp.async.cg.shared.global [%0], [%1], 16;" :: "r"(s), "l"(g) : "memory")
#define CPA_COMMIT() asm volatile("cp.async.commit_group;" ::: "memory")
#define CPA_WAIT2()  asm volatile("cp.async.wait_group 2;" ::: "memory")

// fp16 mma, fp32 accum
__device__ __forceinline__ void mma16n8k16h(float d[4], const uint32_t a[4], const uint32_t b[2]) {
    asm volatile(
        "mma.sync.aligned.m16n8k16.row.col.f32.f16.f16.f32 "
        "{%0,%1,%2,%3}, {%4,%5,%6,%7}, {%8,%9}, {%0,%1,%2,%3};"
        : "+f"(d[0]), "+f"(d[1]), "+f"(d[2]), "+f"(d[3])
        : "r"(a[0]), "r"(a[1]), "r"(a[2]), "r"(a[3]), "r"(b[0]), "r"(b[1]));
}

// ---------------------------------------------------------------------------
// fp16 tensor-core GEMM: C[M,N] = A[M,K]*B[N,K]^T, half in.
// 128x256 block, 8 warps (64x64 warp tile), KT=32, 4-stage single-barrier ring.
// mode=1: fused RoPE (cols<3072), output fp16 to Ch. mode=0: fp32 to Cf.
// ---------------------------------------------------------------------------
#define KT 32
#define HPITCH 40
#define A_HF (128 * HPITCH)                 // 5120 halfs
#define B_HF (256 * HPITCH)                 // 10240 halfs
#define STAGE_HF (A_HF + B_HF)              // 15360 halfs
#define STAGE_B (STAGE_HF * 2)              // 30720 bytes
#define GEMM_SMEM (4 * STAGE_B)             // 122880 B

__device__ __forceinline__ void g_load_stage(uint32_t sdst,
        const __half* __restrict__ A, const __half* __restrict__ Bm,
        int m0, int n0, int k0, int K, int t)
{
#pragma unroll
    for (int i = 0; i < 2; i++) {
        int c = t + (i << 8);
        int row = c >> 2, ch = c & 3;
        CPA16(sdst + (uint32_t)(row * HPITCH + ch * 8) * 2,
              A + (size_t)(m0 + row) * K + k0 + ch * 8);
    }
#pragma unroll
    for (int i = 0; i < 4; i++) {
        int c = t + (i << 8);
        int row = c >> 2, ch = c & 3;
        CPA16(sdst + (uint32_t)(A_HF + row * HPITCH + ch * 8) * 2,
              Bm + (size_t)(n0 + row) * K + k0 + ch * 8);
    }
}

__global__ __launch_bounds__(256, 1)
void gemm_tc(const __half* __restrict__ A, const __half* __restrict__ Bm,
             float* __restrict__ Cf, __half* __restrict__ Ch,
             int M, int N, int K, int mode,
             const float* __restrict__ fc, const float* __restrict__ fs)
{
    extern __shared__ __align__(16) __half smh[];
    const uint32_t sbase = smem_u32(smh);
    const int t = threadIdx.x, wid = t >> 5, lane = t & 31;
    const int q = lane >> 2, tq = lane & 3;
    const int wm = wid & 1, wn = wid >> 1;
    const int m0 = blockIdx.y * 128, n0 = blockIdx.x * 256;

    float d[4][8][4];
#pragma unroll
    for (int mi = 0; mi < 4; mi++)
#pragma unroll
        for (int ni = 0; ni < 8; ni++)
#pragma unroll
            for (int r = 0; r < 4; r++) d[mi][ni][r] = 0.0f;

#pragma unroll
    for (int s = 0; s < 3; s++) {
        g_load_stage(sbase + (uint32_t)s * STAGE_B, A, Bm, m0, n0, s * KT, K, t);
        CPA_COMMIT();
    }

    const int NK = K / KT;
    for (int it = 0; it < NK; it++) {
        CPA_WAIT2();
        __syncthreads();
        const __half* Ah = smh + (it & 3) * STAGE_HF;
        const __half* Bh = Ah + A_HF;

#pragma unroll
        for (int ks = 0; ks < 2; ks++) {
            const int kb = ks * 16;
            uint32_t af[4][4];
#pragma unroll
            for (int mi = 0; mi < 4; mi++) {
                const __half* ap = Ah + (wm * 64 + mi * 16 + q) * HPITCH + kb + 2 * tq;
                af[mi][0] = *(const uint32_t*)ap;
                af[mi][1] = *(const uint32_t*)(ap + 8 * HPITCH);
                af[mi][2] = *(const uint32_t*)(ap + 8);
                af[mi][3] = *(const uint32_t*)(ap + 8 * HPITCH + 8);
            }
            uint32_t bf[8][2];
#pragma unroll
            for (int ni = 0; ni < 8; ni++) {
                const __half* bp = Bh + (wn * 64 + ni * 8 + q) * HPITCH + kb + 2 * tq;
                bf[ni][0] = *(const uint32_t*)bp;
                bf[ni][1] = *(const uint32_t*)(bp + 8);
            }
#pragma unroll
            for (int mi = 0; mi < 4; mi++)
#pragma unroll
                for (int ni = 0; ni < 8; ni++)
                    mma16n8k16h(d[mi][ni], af[mi], bf[ni]);
        }

        const int itp = it + 3;
        if (itp < NK)
            g_load_stage(sbase + (uint32_t)(itp & 3) * STAGE_B, A, Bm, m0, n0, itp * KT, K, t);
        CPA_COMMIT();
    }

    // epilogue
#pragma unroll
    for (int mi = 0; mi < 4; mi++) {
        int row = m0 + wm * 64 + mi * 16 + q;
        int row2 = row + 8;
#pragma unroll
        for (int ni = 0; ni < 8; ni++) {
            int col = n0 + wn * 64 + ni * 8 + 2 * tq;
            float v0 = d[mi][ni][0], v1 = d[mi][ni][1];
            float v2 = d[mi][ni][2], v3 = d[mi][ni][3];
            if (mode) {
                if (col < C_ + KVC) {                 // q or k section: RoPE
                    int i = (col & 127) >> 1;
                    int tp1 = row & (T_ - 1), tp2 = row2 & (T_ - 1);
                    float c1 = fc[tp1 * 64 + i], s1 = fs[tp1 * 64 + i];
                    float c2 = fc[tp2 * 64 + i], s2 = fs[tp2 * 64 + i];
                    float r0 = v0 * c1 - v1 * s1, r1 = v0 * s1 + v1 * c1;
                    float r2 = v2 * c2 - v3 * s2, r3 = v2 * s2 + v3 * c2;
                    v0 = r0; v1 = r1; v2 = r2; v3 = r3;
                }
                *(__half2*)(Ch + (size_t)row  * N + col) = __floats2half2_rn(v0, v1);
                *(__half2*)(Ch + (size_t)row2 * N + col) = __floats2half2_rn(v2, v3);
            } else {
                *(float2*)(Cf + (size_t)row  * N + col) = make_float2(v0, v1);
                *(float2*)(Cf + (size_t)row2 * N + col) = make_float2(v2, v3);
            }
        }
    }
}

// ---------------------------------------------------------------------------
__global__ __launch_bounds__(256)
void round_h(const float4* __restrict__ in, __half2* __restrict__ out, int n4)
{
    for (int i = blockIdx.x * 256 + threadIdx.x; i < n4; i += gridDim.x * 256) {
        float4 v = in[i];
        out[2 * i]     = __floats2half2_rn(v.x, v.y);
        out[2 * i + 1] = __floats2half2_rn(v.z, v.w);
    }
}

// ---------------------------------------------------------------------------
// Flash attention, fully fp16 mma (m16n8k16). BM=128, BN=64, D=128, 8 warps.
// V stored TRANSPOSED in smem (Vst[d][j]) so the f16 B fragment's packed
// k-pairs (k = token j) are contiguous. Softmax in fp32 fragments.
// ---------------------------------------------------------------------------
#define BM 128
#define BN 64
#define QPh 136
#define KPh 136
#define VP  72
#define PPh 72
#define ATT_SMEM ((128*QPh + 64*KPh + 128*VP + 128*PPh) * 2)   // 89088 B

__global__ __launch_bounds__(256, 1)
void attn_mma()
{
    extern __shared__ __align__(16) __half smH[];
    __half* Qs  = smH;                    // [128][136]
    __half* Ks  = Qs + 128 * QPh;         // [64][136]
    __half* Vst = Ks + 64 * KPh;          // [128 dims][72] (transposed)
    __half* Ps  = Vst + 128 * VP;         // [128][72]

    const int t = threadIdx.x, w = t >> 5, lane = t & 31;
    const int q = lane >> 2, tq = lane & 3;
    const int qb = (int)gridDim.x - 1 - (int)blockIdx.x;
    const int h = blockIdx.y, b = blockIdx.z;
    const int kvh = h >> 2;
    const float scale = 0.08838834764831845f;
    const int wr = w * 16;

    // Q tile (fp16)
    {
        const __half* qbase = g_qkvh + ((size_t)(b * T_ + qb * BM)) * QKVN + h * HD;
#pragma unroll
        for (int i = 0; i < 8; i++) {
            int c = t + (i << 8);
            int row = c >> 4, ch = c & 15;
            *(uint4*)(Qs + row * QPh + ch * 8) =
                *(const uint4*)(qbase + (size_t)row * QKVN + ch * 8);
        }
    }
    __syncthreads();

    // hoist Q fragments (fp16: 32 regs)
    uint32_t qf[8][4];
#pragma unroll
    for (int ks = 0; ks < 8; ks++) {
        const __half* qp = Qs + (wr + q) * QPh + ks * 16 + 2 * tq;
        qf[ks][0] = *(const uint32_t*)qp;
        qf[ks][1] = *(const uint32_t*)(qp + 8 * QPh);
        qf[ks][2] = *(const uint32_t*)(qp + 8);
        qf[ks][3] = *(const uint32_t*)(qp + 8 * QPh + 8);
    }

    float o[16][4];
#pragma unroll
    for (int nf = 0; nf < 16; nf++)
#pragma unroll
        for (int r = 0; r < 4; r++) o[nf][r] = 0.0f;
    float m0 = -1e30f, m1 = -1e30f, l0 = 0.0f, l1 = 0.0f;

    const int ntiles = 2 * qb + 2;
    for (int kb = 0; kb < ntiles; kb++) {
        __syncthreads();
        {
            const __half* kbase = g_qkvh + ((size_t)(b * T_ + kb * BN)) * QKVN + C_ + kvh * HD;
            const __half* vbase = kbase + KVC;
            // K: [64][128] natural layout
#pragma unroll
            for (int i = 0; i < 4; i++) {
                int c = t + (i << 8);
                int row = c >> 4, ch = c & 15;
                *(uint4*)(Ks + row * KPh + ch * 8) =
                    *(const uint4*)(kbase + (size_t)row * QKVN + ch * 8);
            }
            // V: transpose into Vst[d][j]
#pragma unroll
            for (int i = 0; i < 4; i++) {
                int c = t + (i << 8);
                int j = c & 63, d0 = (c >> 6) << 3;
                uint4 v = *(const uint4*)(vbase + (size_t)j * QKVN + d0);
                const __half* hv = (const __half*)&v;
#pragma unroll
                for (int ii = 0; ii < 8; ii++)
                    Vst[(d0 + ii) * VP + j] = hv[ii];
            }
        }
        __syncthreads();

        // ---- QK: 8 k16-steps
        float s[8][4];
#pragma unroll
        for (int nf = 0; nf < 8; nf++)
#pragma unroll
            for (int r = 0; r < 4; r++) s[nf][r] = 0.0f;

#pragma unroll
        for (int ks = 0; ks < 8; ks++) {
#pragma unroll
            for (int nf = 0; nf < 8; nf++) {
                const __half* kp = Ks + (nf * 8 + q) * KPh + ks * 16 + 2 * tq;
                uint32_t bb[2] = {*(const uint32_t*)kp, *(const uint32_t*)(kp + 8)};
                mma16n8k16h(s[nf], qf[ks], bb);
            }
        }

#pragma unroll
        for (int nf = 0; nf < 8; nf++)
#pragma unroll
            for (int r = 0; r < 4; r++) s[nf][r] *= scale;

        if (kb >= 2 * qb) {
            int ig0 = qb * BM + wr + q, ig1 = ig0 + 8;
#pragma unroll
            for (int nf = 0; nf < 8; nf++) {
                int jg = kb * BN + nf * 8 + 2 * tq;
                if (jg     > ig0) s[nf][0] = -1e30f;
                if (jg + 1 > ig0) s[nf][1] = -1e30f;
                if (jg     > ig1) s[nf][2] = -1e30f;
                if (jg + 1 > ig1) s[nf][3] = -1e30f;
            }
        }

        // ---- online softmax (fp32 fragments)
        float mx0 = s[0][0], mx1 = s[0][2];
#pragma unroll
        for (int nf = 0; nf < 8; nf++) {
            mx0 = fmaxf(mx0, fmaxf(s[nf][0], s[nf][1]));
            mx1 = fmaxf(mx1, fmaxf(s[nf][2], s[nf][3]));
        }
        mx0 = fmaxf(mx0, __shfl_xor_sync(0xffffffffu, mx0, 1));
        mx0 = fmaxf(mx0, __shfl_xor_sync(0xffffffffu, mx0, 2));
        mx1 = fmaxf(mx1, __shfl_xor_sync(0xffffffffu, mx1, 1));
        mx1 = fmaxf(mx1, __shfl_xor_sync(0xffffffffu, mx1, 2));
        float mn0 = fmaxf(m0, mx0), mn1 = fmaxf(m1, mx1);
        float c0 = __expf(m0 - mn0), c1 = __expf(m1 - mn1);
        float rs0 = 0.0f, rs1 = 0.0f;
#pragma unroll
        for (int nf = 0; nf < 8; nf++) {
            s[nf][0] = __expf(s[nf][0] - mn0);
            s[nf][1] = __expf(s[nf][1] - mn0);
            s[nf][2] = __expf(s[nf][2] - mn1);
            s[nf][3] = __expf(s[nf][3] - mn1);
            rs0 += s[nf][0] + s[nf][1];
            rs1 += s[nf][2] + s[nf][3];
        }
        rs0 += __shfl_xor_sync(0xffffffffu, rs0, 1);
        rs0 += __shfl_xor_sync(0xffffffffu, rs0, 2);
        rs1 += __shfl_xor_sync(0xffffffffu, rs1, 1);
        rs1 += __shfl_xor_sync(0xffffffffu, rs1, 2);
        l0 = l0 * c0 + rs0;  l1 = l1 * c1 + rs1;
        m0 = mn0;  m1 = mn1;
#pragma unroll
        for (int nf = 0; nf < 16; nf++) {
            o[nf][0] *= c0; o[nf][1] *= c0;
            o[nf][2] *= c1; o[nf][3] *= c1;
        }

        // ---- P -> per-warp smem strip (fp16)
#pragma unroll
        for (int nf = 0; nf < 8; nf++) {
            *(__half2*)(Ps + (wr + q) * PPh + nf * 8 + 2 * tq) =
                __floats2half2_rn(s[nf][0], s[nf][1]);
            *(__half2*)(Ps + (wr + q + 8) * PPh + nf * 8 + 2 * tq) =
                __floats2half2_rn(s[nf][2], s[nf][3]);
        }
        __syncwarp();

        // ---- PV: 4 k16-steps over transposed V
#pragma unroll
        for (int ks = 0; ks < 4; ks++) {
            uint32_t a[4];
            const __half* pp = Ps + (wr + q) * PPh + ks * 16 + 2 * tq;
            a[0] = *(const uint32_t*)pp;
            a[1] = *(const uint32_t*)(pp + 8 * PPh);
            a[2] = *(const uint32_t*)(pp + 8);
            a[3] = *(const uint32_t*)(pp + 8 * PPh + 8);
#pragma unroll
            for (int nf = 0; nf < 16; nf++) {
                const __half* vp = Vst + (nf * 8 + q) * VP + ks * 16 + 2 * tq;
                uint32_t bb[2] = {*(const uint32_t*)vp, *(const uint32_t*)(vp + 8)};
                mma16n8k16h(o[nf], a, bb);
            }
        }
    }

    // epilogue: normalize, store fp16 y
    float i0 = 1.0f / l0, i1 = 1.0f / l1;
    int r0 = qb * BM + wr + q;
    __half* yb = g_yh + ((size_t)(b * T_ + r0)) * C_ + h * HD;
#pragma unroll
    for (int nf = 0; nf < 16; nf++) {
        *(__half2*)(yb + nf * 8 + 2 * tq) =
            __floats2half2_rn(o[nf][0] * i0, o[nf][1] * i0);
        *(__half2*)(yb + 8 * C_ + nf * 8 + 2 * tq) =
            __floats2half2_rn(o[nf][2] * i1, o[nf][3] * i1);
    }
}

// ---------------------------------------------------------------------------
extern "C" void kernel_launch(void* const* d_in, const int* in_sizes, int n_in,
                              void* d_out, int out_size)
{
    const float* x  = (const float*)d_in[0];
    const float* fc = (const float*)d_in[1];
    const float* fs = (const float*)d_in[2];
    const float* wq = (const float*)d_in[3];
    const float* wk = (const float*)d_in[4];
    const float* wv = (const float*)d_in[5];
    const float* wo = (const float*)d_in[6];
    float* out = (float*)d_out;

    __half *qkvh, *xh, *wqkvh, *woh, *yh;
    cudaGetSymbolAddress((void**)&qkvh,  g_qkvh);
    cudaGetSymbolAddress((void**)&yh,    g_yh);
    cudaGetSymbolAddress((void**)&xh,    g_xh);
    cudaGetSymbolAddress((void**)&wqkvh, g_wqkvh);
    cudaGetSymbolAddress((void**)&woh,   g_woh);

    round_h<<<2048, 256>>>((const float4*)x,  (__half2*)xh, MROWS * C_ / 4);
    round_h<<<1024, 256>>>((const float4*)wq, (__half2*)wqkvh, C_ * C_ / 4);
    round_h<<<512,  256>>>((const float4*)wk, (__half2*)(wqkvh + (size_t)C_ * C_), KVC * C_ / 4);
    round_h<<<512,  256>>>((const float4*)wv, (__half2*)(wqkvh + (size_t)(C_ + KVC) * C_), KVC * C_ / 4);
    round_h<<<1024, 256>>>((const float4*)wo, (__half2*)woh, C_ * C_ / 4);

    cudaFuncSetAttribute(gemm_tc, cudaFuncAttributeMaxDynamicSharedMemorySize, GEMM_SMEM);

    // fused QKV projection + RoPE -> fp16 qkv
    gemm_tc<<<dim3(QKVN / 256, MROWS / 128), 256, GEMM_SMEM>>>(
        xh, wqkvh, nullptr, qkvh, MROWS, QKVN, C_, 1, fc, fs);

    cudaFuncSetAttribute(attn_mma, cudaFuncAttributeMaxDynamicSharedMemorySize, ATT_SMEM);
    attn_mma<<<dim3(T_ / BM, NH, B_), 256, ATT_SMEM>>>();

    // output projection (fp16 in, fp32 out)
    gemm_tc<<<dim3(C_ / 256, MROWS / 128), 256, GEMM_SMEM>>>(
        yh, woh, out, nullptr, MROWS, C_, C_, 0, nullptr, nullptr);
}

// round 16
// speedup vs baseline: 1.9335x; 1.0656x over previous
#include <cuda_runtime.h>
#include <cuda_fp16.h>
#include <cstdint>

#define B_   2
#define T_   2048
#define C_   2048
#define NH   16
#define NKV  4
#define HD   128
#define MROWS (B_*T_)          // 4096
#define KVC  (NKV*HD)          // 1024
#define QKVN (C_ + 2*KVC)      // 4096 (q | k | v)

__device__ __half g_qkvh[MROWS * QKVN];   // fp16 q|k|v (RoPE'd q,k)
__device__ __half g_yh[MROWS * C_];       // fp16 attention output
__device__ __half g_xh[MROWS * C_];       // fp16 x
__device__ __half g_wqkvh[QKVN * C_];     // fp16 wq|wk|wv
__device__ __half g_woh[C_ * C_];         // fp16 wo

// ---------------------------------------------------------------------------
__device__ __forceinline__ uint32_t smem_u32(const void* p) {
    uint32_t a;
    asm("{ .reg .u64 t; cvta.to.shared.u64 t, %1; cvt.u32.u64 %0, t; }" : "=r"(a) : "l"(p));
    return a;
}
#define CPA16(s, g) asm volatile("cp.async.cg.shared.global [%0], [%1], 16;" :: "r"(s), "l"(g) : "memory")
#define CPA_COMMIT() asm volatile("cp.async.commit_group;" ::: "memory")
#define CPA_WAIT2()  asm volatile("cp.async.wait_group 2;" ::: "memory")

// fp16 mma, fp32 accum
__device__ __forceinline__ void mma16n8k16h(float d[4], const uint32_t a[4], const uint32_t b[2]) {
    asm volatile(
        "mma.sync.aligned.m16n8k16.row.col.f32.f16.f16.f32 "
        "{%0,%1,%2,%3}, {%4,%5,%6,%7}, {%8,%9}, {%0,%1,%2,%3};"
        : "+f"(d[0]), "+f"(d[1]), "+f"(d[2]), "+f"(d[3])
        : "r"(a[0]), "r"(a[1]), "r"(a[2]), "r"(a[3]), "r"(b[0]), "r"(b[1]));
}

// ---------------------------------------------------------------------------
// fp16 tensor-core GEMM: C[M,N] = A[M,K]*B[N,K]^T, half in.
// 128x256 block, 8 warps (64x64 warp tile), KT=64 (4 k16-steps per barrier),
// 4-stage single-barrier ring. mma order identical to KT=32 version.
// mode=1: fused RoPE (cols<3072), output fp16 to Ch. mode=0: fp32 to Cf.
// ---------------------------------------------------------------------------
#define KT 64
#define HPITCH 72
#define A_HF (128 * HPITCH)                 // 9216 halfs
#define B_HF (256 * HPITCH)                 // 18432 halfs
#define STAGE_HF (A_HF + B_HF)              // 27648 halfs
#define STAGE_B (STAGE_HF * 2)              // 55296 bytes
#define GEMM_SMEM (4 * STAGE_B)             // 221184 B

__device__ __forceinline__ void g_load_stage(uint32_t sdst,
        const __half* __restrict__ A, const __half* __restrict__ Bm,
        int m0, int n0, int k0, int K, int t)
{
#pragma unroll
    for (int i = 0; i < 4; i++) {                    // A: 1024 chunks of 16B
        int c = t + (i << 8);
        int row = c >> 3, ch = c & 7;
        CPA16(sdst + (uint32_t)(row * HPITCH + ch * 8) * 2,
              A + (size_t)(m0 + row) * K + k0 + ch * 8);
    }
#pragma unroll
    for (int i = 0; i < 8; i++) {                    // B: 2048 chunks
        int c = t + (i << 8);
        int row = c >> 3, ch = c & 7;
        CPA16(sdst + (uint32_t)(A_HF + row * HPITCH + ch * 8) * 2,
              Bm + (size_t)(n0 + row) * K + k0 + ch * 8);
    }
}

__global__ __launch_bounds__(256, 1)
void gemm_tc(const __half* __restrict__ A, const __half* __restrict__ Bm,
             float* __restrict__ Cf, __half* __restrict__ Ch,
             int M, int N, int K, int mode,
             const float* __restrict__ fc, const float* __restrict__ fs)
{
    extern __shared__ __align__(16) __half smh[];
    const uint32_t sbase = smem_u32(smh);
    const int t = threadIdx.x, wid = t >> 5, lane = t & 31;
    const int q = lane >> 2, tq = lane & 3;
    const int wm = wid & 1, wn = wid >> 1;
    const int m0 = blockIdx.y * 128, n0 = blockIdx.x * 256;

    float d[4][8][4];
#pragma unroll
    for (int mi = 0; mi < 4; mi++)
#pragma unroll
        for (int ni = 0; ni < 8; ni++)
#pragma unroll
            for (int r = 0; r < 4; r++) d[mi][ni][r] = 0.0f;

#pragma unroll
    for (int s = 0; s < 3; s++) {
        g_load_stage(sbase + (uint32_t)s * STAGE_B, A, Bm, m0, n0, s * KT, K, t);
        CPA_COMMIT();
    }

    const int NK = K / KT;                           // 32
    for (int it = 0; it < NK; it++) {
        CPA_WAIT2();
        __syncthreads();
        const __half* Ah = smh + (it & 3) * STAGE_HF;
        const __half* Bh = Ah + A_HF;

#pragma unroll
        for (int ks = 0; ks < 4; ks++) {             // four k16 steps per KT=64
            const int kb = ks * 16;
            uint32_t af[4][4];
#pragma unroll
            for (int mi = 0; mi < 4; mi++) {
                const __half* ap = Ah + (wm * 64 + mi * 16 + q) * HPITCH + kb + 2 * tq;
                af[mi][0] = *(const uint32_t*)ap;
                af[mi][1] = *(const uint32_t*)(ap + 8 * HPITCH);
                af[mi][2] = *(const uint32_t*)(ap + 8);
                af[mi][3] = *(const uint32_t*)(ap + 8 * HPITCH + 8);
            }
            uint32_t bf[8][2];
#pragma unroll
            for (int ni = 0; ni < 8; ni++) {
                const __half* bp = Bh + (wn * 64 + ni * 8 + q) * HPITCH + kb + 2 * tq;
                bf[ni][0] = *(const uint32_t*)bp;
                bf[ni][1] = *(const uint32_t*)(bp + 8);
            }
#pragma unroll
            for (int mi = 0; mi < 4; mi++)
#pragma unroll
                for (int ni = 0; ni < 8; ni++)
                    mma16n8k16h(d[mi][ni], af[mi], bf[ni]);
        }

        const int itp = it + 3;
        if (itp < NK)
            g_load_stage(sbase + (uint32_t)(itp & 3) * STAGE_B, A, Bm, m0, n0, itp * KT, K, t);
        CPA_COMMIT();
    }

    // epilogue
#pragma unroll
    for (int mi = 0; mi < 4; mi++) {
        int row = m0 + wm * 64 + mi * 16 + q;
        int row2 = row + 8;
#pragma unroll
        for (int ni = 0; ni < 8; ni++) {
            int col = n0 + wn * 64 + ni * 8 + 2 * tq;
            float v0 = d[mi][ni][0], v1 = d[mi][ni][1];
            float v2 = d[mi][ni][2], v3 = d[mi][ni][3];
            if (mode) {
                if (col < C_ + KVC) {                 // q or k section: RoPE
                    int i = (col & 127) >> 1;
                    int tp1 = row & (T_ - 1), tp2 = row2 & (T_ - 1);
                    float c1 = fc[tp1 * 64 + i], s1 = fs[tp1 * 64 + i];
                    float c2 = fc[tp2 * 64 + i], s2 = fs[tp2 * 64 + i];
                    float r0 = v0 * c1 - v1 * s1, r1 = v0 * s1 + v1 * c1;
                    float r2 = v2 * c2 - v3 * s2, r3 = v2 * s2 + v3 * c2;
                    v0 = r0; v1 = r1; v2 = r2; v3 = r3;
                }
                *(__half2*)(Ch + (size_t)row  * N + col) = __floats2half2_rn(v0, v1);
                *(__half2*)(Ch + (size_t)row2 * N + col) = __floats2half2_rn(v2, v3);
            } else {
                *(float2*)(Cf + (size_t)row  * N + col) = make_float2(v0, v1);
                *(float2*)(Cf + (size_t)row2 * N + col) = make_float2(v2, v3);
            }
        }
    }
}

// ---------------------------------------------------------------------------
// Fused fp32->fp16 rounding of ALL operands in ONE launch (region dispatch).
// ---------------------------------------------------------------------------
#define N_X4  (MROWS * C_ / 4)      // 2097152
#define N_WQ4 (C_ * C_ / 4)         // 1048576
#define N_WK4 (KVC * C_ / 4)        // 524288

__global__ __launch_bounds__(256)
void round_all(const float4* __restrict__ x,  const float4* __restrict__ wq,
               const float4* __restrict__ wk, const float4* __restrict__ wv,
               const float4* __restrict__ wo,
               __half2* __restrict__ xh, __half2* __restrict__ wqkvh,
               __half2* __restrict__ woh)
{
    const int total = N_X4 + 2 * N_WQ4 + 2 * N_WK4;   // 5242880
    for (int i = blockIdx.x * 256 + threadIdx.x; i < total; i += gridDim.x * 256) {
        const float4* src; __half2* dst; int off;
        if (i < N_X4)                          { src = x;  dst = xh;    off = i; }
        else if (i < N_X4 + N_WQ4)             { src = wq; dst = wqkvh; off = i - N_X4; }
        else if (i < N_X4 + N_WQ4 + N_WK4)     { src = wk; dst = wqkvh + (size_t)C_ * C_ / 2;
                                                 off = i - N_X4 - N_WQ4; }
        else if (i < N_X4 + N_WQ4 + 2 * N_WK4) { src = wv; dst = wqkvh + (size_t)(C_ + KVC) * C_ / 2;
                                                 off = i - N_X4 - N_WQ4 - N_WK4; }
        else                                   { src = wo; dst = woh;
                                                 off = i - N_X4 - N_WQ4 - 2 * N_WK4; }
        float4 v = src[off];
        dst[2 * off]     = __floats2half2_rn(v.x, v.y);
        dst[2 * off + 1] = __floats2half2_rn(v.z, v.w);
    }
}

// ---------------------------------------------------------------------------
// Flash attention, fully fp16 mma (m16n8k16) — unchanged from round 15.
// ---------------------------------------------------------------------------
#define BM 128
#define BN 64
#define QPh 136
#define KPh 136
#define VP  72
#define PPh 72
#define ATT_SMEM ((128*QPh + 64*KPh + 128*VP + 128*PPh) * 2)   // 89088 B

__global__ __launch_bounds__(256, 1)
void attn_mma()
{
    extern __shared__ __align__(16) __half smH[];
    __half* Qs  = smH;
    __half* Ks  = Qs + 128 * QPh;
    __half* Vst = Ks + 64 * KPh;
    __half* Ps  = Vst + 128 * VP;

    const int t = threadIdx.x, w = t >> 5, lane = t & 31;
    const int q = lane >> 2, tq = lane & 3;
    const int qb = (int)gridDim.x - 1 - (int)blockIdx.x;
    const int h = blockIdx.y, b = blockIdx.z;
    const int kvh = h >> 2;
    const float scale = 0.08838834764831845f;
    const int wr = w * 16;

    {
        const __half* qbase = g_qkvh + ((size_t)(b * T_ + qb * BM)) * QKVN + h * HD;
#pragma unroll
        for (int i = 0; i < 8; i++) {
            int c = t + (i << 8);
            int row = c >> 4, ch = c & 15;
            *(uint4*)(Qs + row * QPh + ch * 8) =
                *(const uint4*)(qbase + (size_t)row * QKVN + ch * 8);
        }
    }
    __syncthreads();

    uint32_t qf[8][4];
#pragma unroll
    for (int ks = 0; ks < 8; ks++) {
        const __half* qp = Qs + (wr + q) * QPh + ks * 16 + 2 * tq;
        qf[ks][0] = *(const uint32_t*)qp;
        qf[ks][1] = *(const uint32_t*)(qp + 8 * QPh);
        qf[ks][2] = *(const uint32_t*)(qp + 8);
        qf[ks][3] = *(const uint32_t*)(qp + 8 * QPh + 8);
    }

    float o[16][4];
#pragma unroll
    for (int nf = 0; nf < 16; nf++)
#pragma unroll
        for (int r = 0; r < 4; r++) o[nf][r] = 0.0f;
    float m0 = -1e30f, m1 = -1e30f, l0 = 0.0f, l1 = 0.0f;

    const int ntiles = 2 * qb + 2;
    for (int kb = 0; kb < ntiles; kb++) {
        __syncthreads();
        {
            const __half* kbase = g_qkvh + ((size_t)(b * T_ + kb * BN)) * QKVN + C_ + kvh * HD;
            const __half* vbase = kbase + KVC;
#pragma unroll
            for (int i = 0; i < 4; i++) {
                int c = t + (i << 8);
                int row = c >> 4, ch = c & 15;
                *(uint4*)(Ks + row * KPh + ch * 8) =
                    *(const uint4*)(kbase + (size_t)row * QKVN + ch * 8);
            }
#pragma unroll
            for (int i = 0; i < 4; i++) {
                int c = t + (i << 8);
                int j = c & 63, d0 = (c >> 6) << 3;
                uint4 v = *(const uint4*)(vbase + (size_t)j * QKVN + d0);
                const __half* hv = (const __half*)&v;
#pragma unroll
                for (int ii = 0; ii < 8; ii++)
                    Vst[(d0 + ii) * VP + j] = hv[ii];
            }
        }
        __syncthreads();

        float s[8][4];
#pragma unroll
        for (int nf = 0; nf < 8; nf++)
#pragma unroll
            for (int r = 0; r < 4; r++) s[nf][r] = 0.0f;

#pragma unroll
        for (int ks = 0; ks < 8; ks++) {
#pragma unroll
            for (int nf = 0; nf < 8; nf++) {
                const __half* kp = Ks + (nf * 8 + q) * KPh + ks * 16 + 2 * tq;
                uint32_t bb[2] = {*(const uint32_t*)kp, *(const uint32_t*)(kp + 8)};
                mma16n8k16h(s[nf], qf[ks], bb);
            }
        }

#pragma unroll
        for (int nf = 0; nf < 8; nf++)
#pragma unroll
            for (int r = 0; r < 4; r++) s[nf][r] *= scale;

        if (kb >= 2 * qb) {
            int ig0 = qb * BM + wr + q, ig1 = ig0 + 8;
#pragma unroll
            for (int nf = 0; nf < 8; nf++) {
                int jg = kb * BN + nf * 8 + 2 * tq;
                if (jg     > ig0) s[nf][0] = -1e30f;
                if (jg + 1 > ig0) s[nf][1] = -1e30f;
                if (jg     > ig1) s[nf][2] = -1e30f;
                if (jg + 1 > ig1) s[nf][3] = -1e30f;
            }
        }

        float mx0 = s[0][0], mx1 = s[0][2];
#pragma unroll
        for (int nf = 0; nf < 8; nf++) {
            mx0 = fmaxf(mx0, fmaxf(s[nf][0], s[nf][1]));
            mx1 = fmaxf(mx1, fmaxf(s[nf][2], s[nf][3]));
        }
        mx0 = fmaxf(mx0, __shfl_xor_sync(0xffffffffu, mx0, 1));
        mx0 = fmaxf(mx0, __shfl_xor_sync(0xffffffffu, mx0, 2));
        mx1 = fmaxf(mx1, __shfl_xor_sync(0xffffffffu, mx1, 1));
        mx1 = fmaxf(mx1, __shfl_xor_sync(0xffffffffu, mx1, 2));
        float mn0 = fmaxf(m0, mx0), mn1 = fmaxf(m1, mx1);
        float c0 = __expf(m0 - mn0), c1 = __expf(m1 - mn1);
        float rs0 = 0.0f, rs1 = 0.0f;
#pragma unroll
        for (int nf = 0; nf < 8; nf++) {
            s[nf][0] = __expf(s[nf][0] - mn0);
            s[nf][1] = __expf(s[nf][1] - mn0);
            s[nf][2] = __expf(s[nf][2] - mn1);
            s[nf][3] = __expf(s[nf][3] - mn1);
            rs0 += s[nf][0] + s[nf][1];
            rs1 += s[nf][2] + s[nf][3];
        }
        rs0 += __shfl_xor_sync(0xffffffffu, rs0, 1);
        rs0 += __shfl_xor_sync(0xffffffffu, rs0, 2);
        rs1 += __shfl_xor_sync(0xffffffffu, rs1, 1);
        rs1 += __shfl_xor_sync(0xffffffffu, rs1, 2);
        l0 = l0 * c0 + rs0;  l1 = l1 * c1 + rs1;
        m0 = mn0;  m1 = mn1;
#pragma unroll
        for (int nf = 0; nf < 16; nf++) {
            o[nf][0] *= c0; o[nf][1] *= c0;
            o[nf][2] *= c1; o[nf][3] *= c1;
        }

#pragma unroll
        for (int nf = 0; nf < 8; nf++) {
            *(__half2*)(Ps + (wr + q) * PPh + nf * 8 + 2 * tq) =
                __floats2half2_rn(s[nf][0], s[nf][1]);
            *(__half2*)(Ps + (wr + q + 8) * PPh + nf * 8 + 2 * tq) =
                __floats2half2_rn(s[nf][2], s[nf][3]);
        }
        __syncwarp();

#pragma unroll
        for (int ks = 0; ks < 4; ks++) {
            uint32_t a[4];
            const __half* pp = Ps + (wr + q) * PPh + ks * 16 + 2 * tq;
            a[0] = *(const uint32_t*)pp;
            a[1] = *(const uint32_t*)(pp + 8 * PPh);
            a[2] = *(const uint32_t*)(pp + 8);
            a[3] = *(const uint32_t*)(pp + 8 * PPh + 8);
#pragma unroll
            for (int nf = 0; nf < 16; nf++) {
                const __half* vp = Vst + (nf * 8 + q) * VP + ks * 16 + 2 * tq;
                uint32_t bb[2] = {*(const uint32_t*)vp, *(const uint32_t*)(vp + 8)};
                mma16n8k16h(o[nf], a, bb);
            }
        }
    }

    float i0 = 1.0f / l0, i1 = 1.0f / l1;
    int r0 = qb * BM + wr + q;
    __half* yb = g_yh + ((size_t)(b * T_ + r0)) * C_ + h * HD;
#pragma unroll
    for (int nf = 0; nf < 16; nf++) {
        *(__half2*)(yb + nf * 8 + 2 * tq) =
            __floats2half2_rn(o[nf][0] * i0, o[nf][1] * i0);
        *(__half2*)(yb + 8 * C_ + nf * 8 + 2 * tq) =
            __floats2half2_rn(o[nf][2] * i1, o[nf][3] * i1);
    }
}

// ---------------------------------------------------------------------------
extern "C" void kernel_launch(void* const* d_in, const int* in_sizes, int n_in,
                              void* d_out, int out_size)
{
    const float* x  = (const float*)d_in[0];
    const float* fc = (const float*)d_in[1];
    const float* fs = (const float*)d_in[2];
    const float* wq = (const float*)d_in[3];
    const float* wk = (const float*)d_in[4];
    const float* wv = (const float*)d_in[5];
    const float* wo = (const float*)d_in[6];
    float* out = (float*)d_out;

    __half *qkvh, *xh, *wqkvh, *woh, *yh;
    cudaGetSymbolAddress((void**)&qkvh,  g_qkvh);
    cudaGetSymbolAddress((void**)&yh,    g_yh);
    cudaGetSymbolAddress((void**)&xh,    g_xh);
    cudaGetSymbolAddress((void**)&wqkvh, g_wqkvh);
    cudaGetSymbolAddress((void**)&woh,   g_woh);

    // single fused rounding launch
    round_all<<<2048, 256>>>((const float4*)x, (const float4*)wq, (const float4*)wk,
                             (const float4*)wv, (const float4*)wo,
                             (__half2*)xh, (__half2*)wqkvh, (__half2*)woh);

    cudaFuncSetAttribute(gemm_tc, cudaFuncAttributeMaxDynamicSharedMemorySize, GEMM_SMEM);

    // fused QKV projection + RoPE -> fp16 qkv
    gemm_tc<<<dim3(QKVN / 256, MROWS / 128), 256, GEMM_SMEM>>>(
        xh, wqkvh, nullptr, qkvh, MROWS, QKVN, C_, 1, fc, fs);

    cudaFuncSetAttribute(attn_mma, cudaFuncAttributeMaxDynamicSharedMemorySize, ATT_SMEM);
    attn_mma<<<dim3(T_ / BM, NH, B_), 256, ATT_SMEM>>>();

    // output projection (fp16 in, fp32 out)
    gemm_tc<<<dim3(C_ / 256, MROWS / 128), 256, GEMM_SMEM>>>(
        yh, woh, out, nullptr, MROWS, C_, C_, 0, nullptr, nullptr);
}